// round 13
// baseline (speedup 1.0000x reference)
#include <cuda_runtime.h>

// FlowNetC correlation on GB300 — round 13: fine-grained warp split.
// warp = (par, mt): ONE m16 tile per warp -> 20 acc regs, 4 ldsm + 10 MMA per
// chunk; block = one dy (8 warps, 256 thr); __launch_bounds__(256,3) ->
// 24 warps/SM (6/SMSP) for latency hiding. cp.async 4-stage ring,
// banded m16n8k8 tf32 MMA on pre-converted de-interleaved scratch.
//
// out[b, dy*21+dx, y, x] = (1/256) * sum_c in1[b,c,y,x] * in2[b,c, y+2dy-20, x+2dx-20]

#define DD      21
#define HH      96
#define WW      128
#define NCH     32
#define NTH     256

// smem (words per stage). B: [pr 2][kh 2][u 96][4]; A: [pr 2][kh 2][m 64][4]
#define B_PR    768                 // kh2 * 96 * 4
#define B_KH    384
#define A_BASE  1536                // = 2 * B_PR
#define STAGE   2560                // + A: 2*512
#define NSTG    4
#define SMEM_WORDS (NSTG * STAGE)   // 10240 words = 40960 B
#define STAGE_B (STAGE * 4)

#define ELEMS   (8 * 256 * 96 * 128)
#define CSTEP   (2 * 96 * 2 * 64 * 4)   // +2 c4 per chunk = 98304 floats

__device__ float g1t[ELEMS];   // A scratch (in1 * 1/256, tf32 bits)
__device__ float g2t[ELEMS];   // B scratch (in2, tf32 bits)

__device__ __forceinline__ unsigned cvt_tf32(float v) {
    unsigned r;
    asm("cvt.rna.tf32.f32 %0, %1;" : "=r"(r) : "f"(v));
    return r;
}
__device__ __forceinline__ void cp16(unsigned dst, const float* src) {
    asm volatile("cp.async.cg.shared.global [%0], [%1], 16;"
                 :: "r"(dst), "l"(src));
}
__device__ __forceinline__ void ldsm4(unsigned addr, unsigned& r0, unsigned& r1,
                                      unsigned& r2, unsigned& r3) {
    asm volatile("ldmatrix.sync.aligned.m8n8.x4.shared.b16 {%0,%1,%2,%3}, [%4];"
                 : "=r"(r0), "=r"(r1), "=r"(r2), "=r"(r3) : "r"(addr));
}
__device__ __forceinline__ void mma_tf32(float (&d)[4],
                                         unsigned a0, unsigned a1,
                                         unsigned a2, unsigned a3,
                                         unsigned b0, unsigned b1) {
    asm volatile(
        "mma.sync.aligned.m16n8k8.row.col.f32.tf32.tf32.f32 "
        "{%0,%1,%2,%3}, {%4,%5,%6,%7}, {%8,%9}, {%0,%1,%2,%3};"
        : "+f"(d[0]), "+f"(d[1]), "+f"(d[2]), "+f"(d[3])
        : "r"(a0), "r"(a1), "r"(a2), "r"(a3), "r"(b0), "r"(b1));
}

// ---- prepass: cvt + transpose to [b][c4][y][par][xh][cc4] (uint4 stores) ----
__global__ void __launch_bounds__(128) prepass(const float* __restrict__ s1,
                                               const float* __restrict__ s2)
{
    const int x   = threadIdx.x;        // 0..127
    const int y   = blockIdx.x;         // 96
    const int c4  = blockIdx.y;         // 64
    const int b   = blockIdx.z & 7;
    const bool isA = blockIdx.z >= 8;
    const size_t plane = (size_t)HH * WW;
    const float* src = (isA ? s1 : s2)
        + ((size_t)(b * 256 + c4 * 4) * HH + y) * WW + x;
    const float sc = isA ? (1.0f / 256.0f) : 1.0f;   // exact, baked into A
    unsigned v0 = cvt_tf32(src[0]         * sc);
    unsigned v1 = cvt_tf32(src[plane]     * sc);
    unsigned v2 = cvt_tf32(src[2 * plane] * sc);
    unsigned v3 = cvt_tf32(src[3 * plane] * sc);
    float* dstT = isA ? g1t : g2t;
    size_t o = ((((size_t)b * 64 + c4) * HH + y) * 2 + (x & 1)) * 64 + (x >> 1);
    ((uint4*)dstT)[o] = make_uint4(v0, v1, v2, v3);
}

extern __shared__ unsigned smw[];

__global__ void __launch_bounds__(NTH, 3) corr_mma(float* __restrict__ g_out)
{
    const int b    = blockIdx.z;
    const int y    = blockIdx.y;
    const int dy   = blockIdx.x;      // 0..20 (one dy per block)
    const int tid  = threadIdx.x;
    const int lane = tid & 31;
    const int w    = tid >> 5;        // 0..7
    const int par  = w & 1;
    const int mt   = w >> 1;          // 0..3
    const int g    = lane >> 2;
    const int t    = lane & 3;

    const size_t plane = (size_t)HH * WW;

    // Zero all stages once: pad u-rows (u<10, u>=74) stay zero; if this dy's
    // in2 row is out of range, cp.async is skipped and B stays all-zero.
    for (int i = tid; i < SMEM_WORDS; i += NTH) smw[i] = 0u;

    const unsigned sm0 = (unsigned)__cvta_generic_to_shared(smw);

    const int  row2 = y + 2 * dy - 20;
    const bool rok  = (row2 >= 0) && (row2 < HH);

    // ---- cp.async slots: exactly 2 per thread per chunk (1 B row + 1 A row) ----
    unsigned boff, bdst, aoff, adst;
    {
        int u6 = tid & 63, kh = (tid >> 6) & 1, pr = tid >> 7;
        boff = (unsigned)(((((b * 64 + kh) * HH + (rok ? row2 : 0)) * 2 + pr)
                           * 64 + u6) * 4);
        bdst = sm0 + (unsigned)((pr * B_PR + kh * B_KH + (u6 + 10) * 4) * 4);
        int m = tid & 63;   // same decode for A
        aoff = (unsigned)(((((b * 64 + kh) * HH + y) * 2 + pr) * 64 + m) * 4);
        adst = sm0 + (unsigned)((A_BASE + pr * 512 + kh * 256 + m * 4) * 4);
    }

    // ---- ldmatrix lane bases (byte addresses into stage 0) ----
    const unsigned bl_kh = (lane >> 3) & 1;
    const unsigned bl_u  = ((lane >> 4) << 3) + (lane & 7);
    const unsigned bLds  = sm0 + (par * B_PR + bl_kh * B_KH + bl_u * 4) * 4
                         + (unsigned)mt * 256;          // first tile-pair at jj=mt
    const unsigned al_kh = lane >> 4;
    const unsigned al_m  = ((lane >> 3) & 1) * 8 + (lane & 7);
    const unsigned aLds  = sm0 + (A_BASE + par * 512 + al_kh * 256 + al_m * 4) * 4
                         + (unsigned)mt * 256;

    float acc[5][4];
    #pragma unroll
    for (int f = 0; f < 5; ++f)
        #pragma unroll
        for (int e = 0; e < 4; ++e) acc[f][e] = 0.0f;

    __syncthreads();   // zeroing complete before any cp.async lands

    auto issue_chunk = [&](int stg) {
        const unsigned sb = (unsigned)stg * STAGE_B;
        if (rok) cp16(bdst + sb, (const float*)g2t + boff);
        boff += CSTEP;
        cp16(adst + sb, (const float*)g1t + aoff);
        aoff += CSTEP;
    };

    issue_chunk(0); asm volatile("cp.async.commit_group;");
    issue_chunk(1); asm volatile("cp.async.commit_group;");
    issue_chunk(2); asm volatile("cp.async.commit_group;");

    for (int k = 0; k < NCH; ++k) {
        asm volatile("cp.async.wait_group 2;");   // chunk k complete
        __syncthreads();  // visible to all; all warps finished compute k-1

        if (k + 3 < NCH) issue_chunk((k + 3) & 3);
        asm volatile("cp.async.commit_group;");   // uniform group counting

        const unsigned sb = (unsigned)(k & 3) * STAGE_B;

        // fragments: 1 A-ldsm.x4 + 3 B-ldsm.x4 (tile pairs jj = mt..mt+2)
        unsigned a0, a1, a2, a3;
        ldsm4(aLds + sb, a0, a1, a2, a3);
        unsigned bf[3][4];
        #pragma unroll
        for (int q = 0; q < 3; ++q)
            ldsm4(bLds + sb + q * 256, bf[q][0], bf[q][1], bf[q][2], bf[q][3]);

        // 10 MMAs: band tiles i = 0..4 (j = 2mt+i), plus kh pairs inside frags
        // jj = mt+q covers j0 = 2(mt+q) -> i = 2q, and j1 -> i = 2q+1.
        #pragma unroll
        for (int q = 0; q < 3; ++q) {
            mma_tf32(acc[2 * q], a0, a1, a2, a3, bf[q][0], bf[q][1]);
            if (2 * q + 1 < 5)
                mma_tf32(acc[2 * q + 1], a0, a1, a2, a3, bf[q][2], bf[q][3]);
        }
    }

    // ---- epilogue: band-extract + scatter stores (1/256 pre-baked in A) ----
    float* ob = g_out + ((size_t)(b * (DD * DD) + dy * DD)) * plane
                      + (size_t)y * WW + par;
    #pragma unroll
    for (int i = 0; i < 5; ++i) {
        const int u0 = 8 * (2 * mt + i);
        const float* f = acc[i];
        #pragma unroll
        for (int e = 0; e < 4; ++e) {
            int r   = (e >= 2) ? (g + 8) : g;
            int col = 2 * t + (e & 1);
            int xh  = 16 * mt + r;
            int dx  = u0 + col - xh;
            if (dx >= 0 && dx < DD)
                ob[(size_t)dx * plane + 2 * xh] = f[e];
        }
    }
}

extern "C" void kernel_launch(void* const* d_in, const int* in_sizes, int n_in,
                              void* d_out, int out_size)
{
    (void)in_sizes; (void)n_in; (void)out_size;
    const float* in1 = (const float*)d_in[0];
    const float* in2 = (const float*)d_in[1];
    float*       out = (float*)d_out;

    // kernel 1: convert + transpose both tensors into k-contiguous scratch
    prepass<<<dim3(HH, 64, 16), 128>>>(in1, in2);

    // kernel 2: banded MMA, one dy per block
    cudaFuncSetAttribute(corr_mma, cudaFuncAttributeMaxDynamicSharedMemorySize,
                         SMEM_WORDS * 4);
    dim3 grid(DD, HH, 8);    // (dy, y, b) -> 16128 blocks
    corr_mma<<<grid, NTH, SMEM_WORDS * 4>>>(out);
}

// round 14
// speedup vs baseline: 1.3719x; 1.3719x over previous
#include <cuda_runtime.h>

// FlowNetC correlation on GB300 — round 14: warp-autonomous pipelines.
// ZERO block barriers: each warp cp.asyncs its own B(dyl,par)+A(par) slices
// into a private 3-stage smem ring, synced only by its own wait_group+syncwarp.
// Consumer identical to R9 (4 A-ldsm.x4 + 6 B-ldsm.x4 + 20 banded m16n8k8
// tf32 MMAs per chunk). Prepass provides rna-tf32, parity-deinterleaved,
// k-contiguous scratch; A pre-scaled by 1/256.
//
// out[b, dy*21+dx, y, x] = (1/256) * sum_c in1[b,c,y,x] * in2[b,c, y+2dy-20, x+2dx-20]

#define DD      21
#define HH      96
#define WW      128
#define NCH     32
#define NDY     3
#define NTH     192

// per-warp region (words): B [kh2][u96][4] = 768, A [kh2][m64][4] = 512
#define WSTG    1280                 // words per stage
#define WSTG_B  (WSTG * 4)           // 5120 bytes
#define NSTG    3
#define WREG    (NSTG * WSTG)        // 3840 words per warp
#define SMEM_WORDS (6 * WREG)        // 23040 words = 92160 B per block

#define ELEMS   (8 * 256 * 96 * 128)
#define CSTEP   (2 * 96 * 2 * 64 * 4)   // +2 c4 per chunk = 98304 floats
#define KHSTEP  (96 * 2 * 64 * 4)       // +1 c4 = 49152 floats

__device__ float g1t[ELEMS];   // A scratch (in1 * 1/256, tf32 bits)
__device__ float g2t[ELEMS];   // B scratch (in2, tf32 bits)

__device__ __forceinline__ unsigned cvt_tf32(float v) {
    unsigned r;
    asm("cvt.rna.tf32.f32 %0, %1;" : "=r"(r) : "f"(v));
    return r;
}
__device__ __forceinline__ void cp16(unsigned dst, const float* src) {
    asm volatile("cp.async.cg.shared.global [%0], [%1], 16;"
                 :: "r"(dst), "l"(src));
}
__device__ __forceinline__ void ldsm4(unsigned addr, unsigned& r0, unsigned& r1,
                                      unsigned& r2, unsigned& r3) {
    asm volatile("ldmatrix.sync.aligned.m8n8.x4.shared.b16 {%0,%1,%2,%3}, [%4];"
                 : "=r"(r0), "=r"(r1), "=r"(r2), "=r"(r3) : "r"(addr));
}
__device__ __forceinline__ void mma_tf32(float (&d)[4],
                                         unsigned a0, unsigned a1,
                                         unsigned a2, unsigned a3,
                                         unsigned b0, unsigned b1) {
    asm volatile(
        "mma.sync.aligned.m16n8k8.row.col.f32.tf32.tf32.f32 "
        "{%0,%1,%2,%3}, {%4,%5,%6,%7}, {%8,%9}, {%0,%1,%2,%3};"
        : "+f"(d[0]), "+f"(d[1]), "+f"(d[2]), "+f"(d[3])
        : "r"(a0), "r"(a1), "r"(a2), "r"(a3), "r"(b0), "r"(b1));
}

// ---- prepass: cvt + transpose to [b][c4][y][par][xh][cc4] (uint4 stores) ----
__global__ void __launch_bounds__(128) prepass(const float* __restrict__ s1,
                                               const float* __restrict__ s2)
{
    const int x   = threadIdx.x;        // 0..127
    const int y   = blockIdx.x;         // 96
    const int c4  = blockIdx.y;         // 64
    const int b   = blockIdx.z & 7;
    const bool isA = blockIdx.z >= 8;
    const size_t plane = (size_t)HH * WW;
    const float* src = (isA ? s1 : s2)
        + ((size_t)(b * 256 + c4 * 4) * HH + y) * WW + x;
    const float sc = isA ? (1.0f / 256.0f) : 1.0f;   // exact, baked into A
    unsigned v0 = cvt_tf32(src[0]         * sc);
    unsigned v1 = cvt_tf32(src[plane]     * sc);
    unsigned v2 = cvt_tf32(src[2 * plane] * sc);
    unsigned v3 = cvt_tf32(src[3 * plane] * sc);
    float* dstT = isA ? g1t : g2t;
    size_t o = ((((size_t)b * 64 + c4) * HH + y) * 2 + (x & 1)) * 64 + (x >> 1);
    ((uint4*)dstT)[o] = make_uint4(v0, v1, v2, v3);
}

extern __shared__ unsigned smw[];

__global__ void __launch_bounds__(NTH, 2) corr_mma(float* __restrict__ g_out)
{
    const int b    = blockIdx.z;
    const int y    = blockIdx.y;
    const int dyg  = blockIdx.x;      // 0..6
    const int tid  = threadIdx.x;
    const int lane = tid & 31;
    const int w    = tid >> 5;        // 0..5
    const int par  = w & 1;
    const int dyl  = w >> 1;          // 0..2
    const int dy   = dyg * NDY + dyl;
    const int g    = lane >> 2;
    const int t    = lane & 3;

    const size_t plane = (size_t)HH * WW;
    const int wb = w * WREG;          // warp's smem region base (words)

    // Each warp zeros ONLY its own region (pads + OOB rows stay zero).
    for (int i = lane; i < WREG; i += 32) smw[wb + i] = 0u;
    __syncwarp();

    const unsigned sm0 = (unsigned)__cvta_generic_to_shared(smw);
    const unsigned wbB = sm0 + (unsigned)wb * 4u;     // warp base, bytes

    const int  row2 = y + 2 * dy - 20;
    const bool rok  = (row2 >= 0) && (row2 < HH);

    // ---- per-lane cp.async bases (8 copies per chunk: 4 B + 4 A) ----
    // B row (kh, u6): src ((((b*64 + 2k+kh)*96 + row2)*2 + par)*64 + u6)*4
    const float* bsrc = g2t + ((size_t)(((b * 64) * HH + (rok ? row2 : 0)) * 2
                                        + par) * 64 + lane) * 4;
    const unsigned bdst = wbB + (unsigned)((10 + lane) * 4) * 4u;
    // A row (kh, m): src ((((b*64 + 2k+kh)*96 + y)*2 + par)*64 + m)*4
    const float* asrc = g1t + ((size_t)(((b * 64) * HH + y) * 2
                                        + par) * 64 + lane) * 4;
    const unsigned adst = wbB + (unsigned)(768 + lane * 4) * 4u;

    // ---- ldmatrix lane bases (bytes, stage 0 of own region) ----
    const unsigned bl_kh = (lane >> 3) & 1;
    const unsigned bl_u  = ((lane >> 4) << 3) + (lane & 7);
    const unsigned bLds  = wbB + (bl_kh * 384 + bl_u * 4) * 4u;
    const unsigned al_kh = lane >> 4;
    const unsigned al_m  = ((lane >> 3) & 1) * 8 + (lane & 7);
    const unsigned aLds  = wbB + (768 + al_kh * 256 + al_m * 4) * 4u;

    float acc[20][4];
    #pragma unroll
    for (int f = 0; f < 20; ++f)
        #pragma unroll
        for (int e = 0; e < 4; ++e) acc[f][e] = 0.0f;

    const float* bp = bsrc;
    const float* ap = asrc;
    auto issue_chunk = [&](int stg) {
        const unsigned sb = (unsigned)stg * WSTG_B;
        if (rok) {
            cp16(bdst + sb,               bp);              // kh0, u6=lane
            cp16(bdst + sb + 512,         bp + 128);        // kh0, u6=lane+32
            cp16(bdst + sb + 1536,        bp + KHSTEP);     // kh1, u6=lane
            cp16(bdst + sb + 1536 + 512,  bp + KHSTEP + 128);
        }
        bp += CSTEP;
        cp16(adst + sb,              ap);                   // kh0, m=lane
        cp16(adst + sb + 512,        ap + 128);             // kh0, m=lane+32
        cp16(adst + sb + 1024,       ap + KHSTEP);          // kh1, m=lane
        cp16(adst + sb + 1024 + 512, ap + KHSTEP + 128);
        ap += CSTEP;
    };

    issue_chunk(0); asm volatile("cp.async.commit_group;");
    issue_chunk(1); asm volatile("cp.async.commit_group;");
    issue_chunk(2); asm volatile("cp.async.commit_group;");

    int stg = 0;
    for (int k = 0; k < NCH; ++k) {
        asm volatile("cp.async.wait_group 2;");   // own chunk-k copies done
        __syncwarp();                             // all lanes of warp passed wait

        const unsigned sb = (unsigned)stg * WSTG_B;

        // A fragments: 4 ldmatrix.x4 (one per m16 tile)
        unsigned a[4][4];
        #pragma unroll
        for (int mt = 0; mt < 4; ++mt)
            ldsm4(aLds + sb + mt * 256, a[mt][0], a[mt][1], a[mt][2], a[mt][3]);

        // B fragments + MMAs (j-outer, tile pair per ldsm.x4)
        #pragma unroll
        for (int jp = 0; jp < 6; ++jp) {
            unsigned b0, b1, b2, b3;
            ldsm4(bLds + sb + jp * 256, b0, b1, b2, b3);
            const int j0 = 2 * jp;
            #pragma unroll
            for (int mt = 0; mt < 4; ++mt)
                if (2 * mt <= j0 && j0 <= 2 * mt + 4)
                    mma_tf32(acc[mt * 5 + (j0 - 2 * mt)],
                             a[mt][0], a[mt][1], a[mt][2], a[mt][3], b0, b1);
            const int j1 = j0 + 1;
            if (j1 < 11) {
                #pragma unroll
                for (int mt = 0; mt < 4; ++mt)
                    if (2 * mt <= j1 && j1 <= 2 * mt + 4)
                        mma_tf32(acc[mt * 5 + (j1 - 2 * mt)],
                                 a[mt][0], a[mt][1], a[mt][2], a[mt][3], b2, b3);
            }
        }

        // refill freed stage AFTER this chunk's MMAs (WAR-safe: MMA issue
        // implies its LDSMs completed; asm volatile keeps textual order)
        if (k + 3 < NCH) issue_chunk(stg);
        asm volatile("cp.async.commit_group;");   // uniform group counting

        stg = (stg == 2) ? 0 : stg + 1;
    }

    // ---- epilogue: band-extract + scatter stores (1/256 pre-baked in A) ----
    float* ob = g_out + ((size_t)(b * (DD * DD) + dy * DD)) * plane
                      + (size_t)y * WW + par;
    #pragma unroll
    for (int mt = 0; mt < 4; ++mt) {
        #pragma unroll
        for (int i = 0; i < 5; ++i) {
            const int u0 = 8 * (2 * mt + i);
            const float* f = acc[mt * 5 + i];
            #pragma unroll
            for (int e = 0; e < 4; ++e) {
                int r   = (e >= 2) ? (g + 8) : g;
                int col = 2 * t + (e & 1);
                int xh  = 16 * mt + r;
                int dx  = u0 + col - xh;
                if (dx >= 0 && dx < DD)
                    ob[(size_t)dx * plane + 2 * xh] = f[e];
            }
        }
    }
}

extern "C" void kernel_launch(void* const* d_in, const int* in_sizes, int n_in,
                              void* d_out, int out_size)
{
    (void)in_sizes; (void)n_in; (void)out_size;
    const float* in1 = (const float*)d_in[0];
    const float* in2 = (const float*)d_in[1];
    float*       out = (float*)d_out;

    // kernel 1: convert + transpose both tensors into k-contiguous scratch
    prepass<<<dim3(HH, 64, 16), 128>>>(in1, in2);

    // kernel 2: banded MMA, warp-autonomous
    cudaFuncSetAttribute(corr_mma, cudaFuncAttributeMaxDynamicSharedMemorySize,
                         SMEM_WORDS * 4);
    dim3 grid(7, HH, 8);     // (dy-group of 3, y, b) -> 5376 blocks
    corr_mma<<<grid, NTH, SMEM_WORDS * 4>>>(out);
}